// round 2
// baseline (speedup 1.0000x reference)
#include <cuda_runtime.h>
#include <math.h>
#include <float.h>

#define N_SAMPLES 8192
#define DIM 128
#define DIM4 32            // DIM/4
#define NCLUST 64
#define BI 128             // rows per block in main kernel
#define NJ 16              // j-chunks
#define JCHUNK (N_SAMPLES / NJ)   // 512
#define TJ 16              // j-tile staged in shared
#define SPAD 65            // padded cluster stride (bank-conflict free)

// Scratch (device globals -- no allocation allowed)
__device__ int   g_lab[N_SAMPLES];
__device__ float g_sq[N_SAMPLES];
__device__ int   g_counts[NCLUST];
// Layout: [chunk][cluster][row]  -> coalesced epilogue reads
__device__ float g_Spart[NJ * NCLUST * N_SAMPLES];
__device__ float g_partial[32];

// ---------------------------------------------------------------------------
// Normalize labels to int32 regardless of whether the harness buffer holds
// int32 or int64. int64 little-endian => odd 32-bit words (high halves) are 0.
__global__ void conv_labels_kernel(const int* __restrict__ Lraw) {
    __shared__ int is64;
    if (threadIdx.x == 0) {
        int odd_or = 0;
        int even_bad = 0;
        for (int k = 0; k < 256; k += 2) {
            odd_or   |= Lraw[k + 1];
            even_bad |= ((unsigned)Lraw[k] >= NCLUST);
        }
        is64 = (odd_or == 0 && !even_bad) ? 1 : 0;
        for (int c = 0; c < NCLUST; c++) g_counts[c] = 0;
    }
    __syncthreads();
    const int w = is64;
    for (int i = threadIdx.x; i < N_SAMPLES; i += blockDim.x) {
        int v = w ? Lraw[2 * i] : Lraw[i];
        v = min(max(v, 0), NCLUST - 1);
        g_lab[i] = v;
    }
}

// sq norms + cluster counts (int atomics: deterministic)
__global__ void prep_kernel(const float* __restrict__ F) {
    int row = blockIdx.x * blockDim.x + threadIdx.x;
    if (row >= N_SAMPLES) return;
    const float4* f4 = reinterpret_cast<const float4*>(F) + row * DIM4;
    float s0 = 0.f, s1 = 0.f, s2 = 0.f, s3 = 0.f;
#pragma unroll
    for (int k = 0; k < DIM4; k++) {
        float4 v = __ldg(&f4[k]);
        s0 = fmaf(v.x, v.x, s0);
        s1 = fmaf(v.y, v.y, s1);
        s2 = fmaf(v.z, v.z, s2);
        s3 = fmaf(v.w, v.w, s3);
    }
    g_sq[row] = (s0 + s1) + (s2 + s3);
    atomicAdd(&g_counts[g_lab[row]], 1);
}

// ---------------------------------------------------------------------------
// Main: block = (i-tile of 128 rows) x (j-chunk of 512 cols).
// Each thread owns one row i; j-features staged in shared and broadcast.
__global__ __launch_bounds__(BI) void dist_kernel(const float* __restrict__ F) {
    const int tid = threadIdx.x;
    const int rowBase = blockIdx.x * BI;
    const int row = rowBase + tid;
    const int jc = blockIdx.y;
    const int j0 = jc * JCHUNK;

    __shared__ float smemS[BI * SPAD];
    __shared__ float4 sjf[TJ * DIM4];
    __shared__ float ssq[TJ];
    __shared__ int   sjl[TJ];

    for (int c = tid; c < BI * SPAD; c += BI) smemS[c] = 0.f;

    // i-row into registers
    float4 xi[DIM4];
    const float4* f4 = reinterpret_cast<const float4*>(F);
#pragma unroll
    for (int k = 0; k < DIM4; k++) xi[k] = __ldg(&f4[row * DIM4 + k]);
    const float sqi = g_sq[row];

    for (int jt = 0; jt < JCHUNK; jt += TJ) {
        __syncthreads();
        for (int idx = tid; idx < TJ * DIM4; idx += BI) {
            int jj = idx / DIM4, k = idx % DIM4;
            sjf[idx] = f4[(size_t)(j0 + jt + jj) * DIM4 + k];
        }
        if (tid < TJ) {
            sjl[tid] = g_lab[j0 + jt + tid];
            ssq[tid] = g_sq[j0 + jt + tid];
        }
        __syncthreads();

#pragma unroll 1
        for (int jj = 0; jj < TJ; jj++) {
            float a0 = 0.f, a1 = 0.f, a2 = 0.f, a3 = 0.f;
            const float4* bj = &sjf[jj * DIM4];
#pragma unroll
            for (int k = 0; k < DIM4; k++) {
                float4 b = bj[k];
                a0 = fmaf(xi[k].x, b.x, a0);
                a1 = fmaf(xi[k].y, b.y, a1);
                a2 = fmaf(xi[k].z, b.z, a2);
                a3 = fmaf(xi[k].w, b.w, a3);
            }
            float dot = (a0 + a1) + (a2 + a3);
            float d2 = sqi + ssq[jj] - 2.f * dot;
            float d = (d2 > 0.f) ? sqrtf(d2) : 0.f;
            smemS[tid * SPAD + sjl[jj]] += d;
        }
    }
    __syncthreads();

    // write [chunk][c][i]; consecutive idx -> consecutive i (coalesced),
    // smem read stride SPAD=65 -> conflict-free
    for (int idx = tid; idx < BI * NCLUST; idx += BI) {
        int c = idx >> 7;        // idx / 128
        int il = idx & 127;      // idx % 128
        g_Spart[(size_t)(jc * NCLUST + c) * N_SAMPLES + rowBase + il] =
            smemS[il * SPAD + c];
    }
}

// ---------------------------------------------------------------------------
__global__ void epilogue_kernel() {
    const int i = blockIdx.x * 256 + threadIdx.x;
    __shared__ int scounts[NCLUST];
    if (threadIdx.x < NCLUST) scounts[threadIdx.x] = g_counts[threadIdx.x];
    __syncthreads();

    const int own = g_lab[i];
    float Sown = 0.f;
    float b = FLT_MAX;
#pragma unroll 1
    for (int c = 0; c < NCLUST; c++) {
        float s = 0.f;
#pragma unroll
        for (int ch = 0; ch < NJ; ch++)
            s += g_Spart[(size_t)(ch * NCLUST + c) * N_SAMPLES + i];
        int cnt = scounts[c];
        if (c == own) {
            Sown = s;
        } else if (cnt > 0) {
            b = fminf(b, s / (float)cnt);
        }
    }
    const int ocnt = scounts[own];
    const float a = Sown / fmaxf((float)ocnt - 1.f, 1.f);
    float score = 0.f;
    if (ocnt > 1) score = (b - a) / fmaxf(b, a);

    __shared__ float red[256];
    red[threadIdx.x] = score;
    __syncthreads();
    for (int s = 128; s > 0; s >>= 1) {
        if (threadIdx.x < s) red[threadIdx.x] += red[threadIdx.x + s];
        __syncthreads();
    }
    if (threadIdx.x == 0) g_partial[blockIdx.x] = red[0];
}

__global__ void final_kernel(float* out) {
    if (threadIdx.x == 0) {
        float s = 0.f;
#pragma unroll
        for (int b = 0; b < 32; b++) s += g_partial[b];
        out[0] = s / (float)N_SAMPLES;
    }
}

// ---------------------------------------------------------------------------
extern "C" void kernel_launch(void* const* d_in, const int* in_sizes, int n_in,
                              void* d_out, int out_size) {
    const float* F = (const float*)d_in[0];
    const int* Lraw = (const int*)d_in[1];
    float* out = (float*)d_out;

    conv_labels_kernel<<<1, 256>>>(Lraw);
    prep_kernel<<<N_SAMPLES / 256, 256>>>(F);
    dim3 grid(N_SAMPLES / BI, NJ);
    dist_kernel<<<grid, BI>>>(F);
    epilogue_kernel<<<N_SAMPLES / 256, 256>>>();
    final_kernel<<<1, 32>>>(out);
}

// round 3
// speedup vs baseline: 1.0548x; 1.0548x over previous
#include <cuda_runtime.h>
#include <math.h>
#include <float.h>

#define N_SAMPLES 8192
#define DIM 128
#define DIM4 32            // DIM/4
#define NCLUST 64
#define BI 128             // rows per block in main kernel
#define NJ 32              // j-chunks
#define JCHUNK (N_SAMPLES / NJ)   // 256
#define TJ 16              // j-tile staged in shared
#define SPAD 65            // padded cluster stride (bank-conflict free)

// Scratch (device globals -- no allocation allowed)
__device__ int   g_lab[N_SAMPLES];
__device__ float g_sq[N_SAMPLES];
__device__ int   g_counts[NCLUST];
// Layout: [chunk][cluster][row]  -> coalesced reduction reads
__device__ float g_Spart[NJ * NCLUST * N_SAMPLES];
__device__ float g_S[NCLUST * N_SAMPLES];     // reduced per-cluster sums
__device__ float g_partial[32];

// packed f32x2 helpers (sm_103a: single fma-pipe instr, 2 MACs/lane)
__device__ __forceinline__ void fma2(unsigned long long& acc,
                                     unsigned long long a,
                                     unsigned long long b) {
    asm("fma.rn.f32x2 %0, %1, %2, %0;" : "+l"(acc) : "l"(a), "l"(b));
}
__device__ __forceinline__ void add2(unsigned long long& a, unsigned long long b) {
    asm("add.rn.f32x2 %0, %0, %1;" : "+l"(a) : "l"(b));
}

// ---------------------------------------------------------------------------
// Normalize labels to int32 whether the buffer holds int32 or int64.
// int64 little-endian => odd 32-bit words (high halves) are 0.
__global__ void conv_labels_kernel(const int* __restrict__ Lraw) {
    __shared__ int is64;
    if (threadIdx.x == 0) {
        int odd_or = 0, even_bad = 0;
        for (int k = 0; k < 256; k += 2) {
            odd_or   |= Lraw[k + 1];
            even_bad |= ((unsigned)Lraw[k] >= NCLUST);
        }
        is64 = (odd_or == 0 && !even_bad) ? 1 : 0;
        for (int c = 0; c < NCLUST; c++) g_counts[c] = 0;
    }
    __syncthreads();
    const int w = is64;
    for (int i = threadIdx.x; i < N_SAMPLES; i += blockDim.x) {
        int v = w ? Lraw[2 * i] : Lraw[i];
        g_lab[i] = min(max(v, 0), NCLUST - 1);
    }
}

// sq norms + cluster counts (int atomics: deterministic)
__global__ void prep_kernel(const float* __restrict__ F) {
    int row = blockIdx.x * blockDim.x + threadIdx.x;
    if (row >= N_SAMPLES) return;
    const float4* f4 = reinterpret_cast<const float4*>(F) + row * DIM4;
    float s0 = 0.f, s1 = 0.f, s2 = 0.f, s3 = 0.f;
#pragma unroll
    for (int k = 0; k < DIM4; k++) {
        float4 v = __ldg(&f4[k]);
        s0 = fmaf(v.x, v.x, s0);
        s1 = fmaf(v.y, v.y, s1);
        s2 = fmaf(v.z, v.z, s2);
        s3 = fmaf(v.w, v.w, s3);
    }
    g_sq[row] = (s0 + s1) + (s2 + s3);
    atomicAdd(&g_counts[g_lab[row]], 1);
}

// ---------------------------------------------------------------------------
// Main: block = (i-tile of 128 rows) x (j-chunk of 256 cols).
// Each thread owns row i (held as 64 packed f32x2 in regs); j-rows broadcast
// from shared; dot products via packed fma.rn.f32x2 (2 MACs/lane/instr).
__global__ __launch_bounds__(BI, 3) void dist_kernel(const float* __restrict__ F) {
    const int tid = threadIdx.x;
    const int rowBase = blockIdx.x * BI;
    const int row = rowBase + tid;
    const int jc = blockIdx.y;
    const int j0 = jc * JCHUNK;

    __shared__ float smemS[BI * SPAD];
    __shared__ float4 sjf[TJ * DIM4];
    __shared__ float ssq[TJ];
    __shared__ int   sjl[TJ];

    for (int c = tid; c < BI * SPAD; c += BI) smemS[c] = 0.f;

    // i-row into registers as 64 packed pairs
    unsigned long long xi2[2 * DIM4];
    const ulonglong2* fp = reinterpret_cast<const ulonglong2*>(F) + (size_t)row * DIM4;
#pragma unroll
    for (int k = 0; k < DIM4; k++) {
        ulonglong2 v = __ldg(&fp[k]);
        xi2[2 * k]     = v.x;
        xi2[2 * k + 1] = v.y;
    }
    const float sqi = g_sq[row];
    const float4* f4 = reinterpret_cast<const float4*>(F);

    for (int jt = 0; jt < JCHUNK; jt += TJ) {
        __syncthreads();
        for (int idx = tid; idx < TJ * DIM4; idx += BI) {
            int jj = idx / DIM4, k = idx % DIM4;
            sjf[idx] = f4[(size_t)(j0 + jt + jj) * DIM4 + k];
        }
        if (tid < TJ) {
            sjl[tid] = g_lab[j0 + jt + tid];
            ssq[tid] = g_sq[j0 + jt + tid];
        }
        __syncthreads();

#pragma unroll 1
        for (int jj = 0; jj < TJ; jj++) {
            const ulonglong2* bj =
                reinterpret_cast<const ulonglong2*>(&sjf[jj * DIM4]);
            unsigned long long a0 = 0ull, a1 = 0ull, a2 = 0ull, a3 = 0ull;
#pragma unroll
            for (int k = 0; k < DIM4; k += 2) {
                ulonglong2 b0 = bj[k];
                ulonglong2 b1 = bj[k + 1];
                fma2(a0, xi2[2 * k],     b0.x);
                fma2(a1, xi2[2 * k + 1], b0.y);
                fma2(a2, xi2[2 * k + 2], b1.x);
                fma2(a3, xi2[2 * k + 3], b1.y);
            }
            add2(a0, a1);
            add2(a2, a3);
            add2(a0, a2);
            float lo = __uint_as_float((unsigned)(a0 & 0xffffffffull));
            float hi = __uint_as_float((unsigned)(a0 >> 32));
            float dot = lo + hi;
            float d2 = sqi + ssq[jj] - 2.f * dot;
            float d = (d2 > 0.f) ? sqrtf(d2) : 0.f;
            smemS[tid * SPAD + sjl[jj]] += d;
        }
    }
    __syncthreads();

    // write [chunk][c][i]; consecutive idx -> consecutive i (coalesced),
    // smem read stride SPAD=65 -> conflict-free
    for (int idx = tid; idx < BI * NCLUST; idx += BI) {
        int c = idx >> 7;
        int il = idx & 127;
        g_Spart[(size_t)(jc * NCLUST + c) * N_SAMPLES + rowBase + il] =
            smemS[il * SPAD + c];
    }
}

// ---------------------------------------------------------------------------
// Stage A: reduce NJ chunk-partials -> g_S[c][i]. One thread per (c,i).
__global__ void reduce_kernel() {
    const int t = blockIdx.x * 256 + threadIdx.x;   // t = c*8192 + i
    float s = 0.f;
#pragma unroll
    for (int ch = 0; ch < NJ; ch++)
        s += g_Spart[(size_t)ch * NCLUST * N_SAMPLES + t];
    g_S[t] = s;
}

// Stage B: per-sample silhouette score + block partial sums.
__global__ void score_kernel() {
    const int i = blockIdx.x * 256 + threadIdx.x;
    __shared__ int scounts[NCLUST];
    if (threadIdx.x < NCLUST) scounts[threadIdx.x] = g_counts[threadIdx.x];
    __syncthreads();

    const int own = g_lab[i];
    float Sown = 0.f;
    float b = FLT_MAX;
#pragma unroll
    for (int c = 0; c < NCLUST; c++) {
        float s = g_S[(size_t)c * N_SAMPLES + i];
        int cnt = scounts[c];
        if (c == own) {
            Sown = s;
        } else if (cnt > 0) {
            b = fminf(b, s / (float)cnt);
        }
    }
    const int ocnt = scounts[own];
    const float a = Sown / fmaxf((float)ocnt - 1.f, 1.f);
    float score = 0.f;
    if (ocnt > 1) score = (b - a) / fmaxf(b, a);

    __shared__ float red[256];
    red[threadIdx.x] = score;
    __syncthreads();
    for (int s = 128; s > 0; s >>= 1) {
        if (threadIdx.x < s) red[threadIdx.x] += red[threadIdx.x + s];
        __syncthreads();
    }
    if (threadIdx.x == 0) g_partial[blockIdx.x] = red[0];
}

__global__ void final_kernel(float* out) {
    if (threadIdx.x == 0) {
        float s = 0.f;
#pragma unroll
        for (int b = 0; b < 32; b++) s += g_partial[b];
        out[0] = s / (float)N_SAMPLES;
    }
}

// ---------------------------------------------------------------------------
extern "C" void kernel_launch(void* const* d_in, const int* in_sizes, int n_in,
                              void* d_out, int out_size) {
    const float* F = (const float*)d_in[0];
    const int* Lraw = (const int*)d_in[1];
    float* out = (float*)d_out;

    conv_labels_kernel<<<1, 256>>>(Lraw);
    prep_kernel<<<N_SAMPLES / 256, 256>>>(F);
    dim3 grid(N_SAMPLES / BI, NJ);
    dist_kernel<<<grid, BI>>>(F);
    reduce_kernel<<<NCLUST * N_SAMPLES / 256, 256>>>();
    score_kernel<<<N_SAMPLES / 256, 256>>>();
    final_kernel<<<1, 32>>>(out);
}

// round 5
// speedup vs baseline: 1.1162x; 1.0582x over previous
#include <cuda_runtime.h>
#include <math.h>
#include <float.h>
#include <stdint.h>

#define N_SAMPLES 8192
#define DIM 128
#define NCLUST 64
#define TILE 128
#define NGROUP 16
#define TPG 4                     // j-tiles per block
#define SPAD 65
#define KSTR 132                  // padded k-major row stride (floats)

// ---- device scratch ----
__device__ int   g_lab[N_SAMPLES];     // normalized labels (input order)
__device__ int   g_labS[N_SAMPLES];    // sorted labels
__device__ int   g_perm[N_SAMPLES];
__device__ float g_sqS[N_SAMPLES];     // sq norms, sorted order
__device__ float g_Fp[N_SAMPLES * DIM];// features, sorted order
__device__ int   g_counts[NCLUST];
__device__ float g_Spart[NGROUP * NCLUST * N_SAMPLES];
__device__ float g_S[NCLUST * N_SAMPLES];
__device__ float g_partial[32];

typedef unsigned long long ull;

__device__ __forceinline__ void fma2(ull& acc, ull a, ull b) {
    asm("fma.rn.f32x2 %0, %1, %2, %0;" : "+l"(acc) : "l"(a), "l"(b));
}
__device__ __forceinline__ ull dup2(float a) {
    ull r;
    asm("mov.b64 %0, {%1, %1};" : "=l"(r) : "f"(a));
    return r;
}

// ---------------------------------------------------------------------------
// Normalize labels to int32 whether buffer holds int32 or int64 (LE: odd
// words zero).
__global__ void conv_labels_kernel(const int* __restrict__ Lraw) {
    __shared__ int is64;
    if (threadIdx.x == 0) {
        int odd_or = 0, even_bad = 0;
        for (int k = 0; k < 256; k += 2) {
            odd_or   |= Lraw[k + 1];
            even_bad |= ((unsigned)Lraw[k] >= NCLUST);
        }
        is64 = (odd_or == 0 && !even_bad) ? 1 : 0;
    }
    __syncthreads();
    const int w = is64;
    for (int i = threadIdx.x; i < N_SAMPLES; i += blockDim.x) {
        int v = w ? Lraw[2 * i] : Lraw[i];
        g_lab[i] = min(max(v, 0), NCLUST - 1);
    }
}

// Deterministic counting sort by label: 256 segments x 32 elements.
__global__ void sort_kernel() {
    __shared__ unsigned short T[256][NCLUST];   // 32KB
    __shared__ int colTot[NCLUST];
    __shared__ int cbase[NCLUST];
    const int s = threadIdx.x;

#pragma unroll
    for (int c = 0; c < NCLUST; c++) T[s][c] = 0;
    const int e0 = s * 32;
    for (int e = 0; e < 32; e++) T[s][g_lab[e0 + e]]++;
    __syncthreads();

    if (s < NCLUST) {
        int tot = 0;
        for (int q = 0; q < 256; q++) tot += T[q][s];
        colTot[s] = tot;
        g_counts[s] = tot;
    }
    __syncthreads();
    if (s == 0) {
        int run = 0;
        for (int c = 0; c < NCLUST; c++) { cbase[c] = run; run += colTot[c]; }
    }
    __syncthreads();
    if (s < NCLUST) {
        int run = cbase[s];
        for (int q = 0; q < 256; q++) {
            int w = T[q][s];
            T[q][s] = (unsigned short)run;
            run += w;
        }
    }
    __syncthreads();
    for (int e = 0; e < 32; e++) {
        int idx = e0 + e;
        int c = g_lab[idx];
        int p = T[s][c]++;
        g_perm[p] = idx;
        g_labS[p] = c;
    }
}

// Gather features into sorted order + per-row sq norms.
// block = 8 rows x 32 lanes.
__global__ void gather_kernel(const float* __restrict__ F) {
    const int lane = threadIdx.x & 31;
    const int p = blockIdx.x * 8 + (threadIdx.x >> 5);
    const int src = g_perm[p];
    float4 v = reinterpret_cast<const float4*>(F)[src * 32 + lane];
    reinterpret_cast<float4*>(g_Fp)[p * 32 + lane] = v;
    float s = v.x * v.x + v.y * v.y + v.z * v.z + v.w * v.w;
#pragma unroll
    for (int o = 16; o > 0; o >>= 1) s += __shfl_down_sync(0xffffffffu, s, o);
    if (lane == 0) g_sqS[p] = s;
}

// ---------------------------------------------------------------------------
// Load a 128x128 fp32 tile k-major transposed into smem: dst[k][row], row
// stride KSTR. 256 threads: thread t handles row r=t>>1, k-half t&1.
__device__ __forceinline__ void load_tile_t(float* dst, const float* __restrict__ src,
                                            int row0, int tid) {
    const int r = tid >> 1;
    const int kh = (tid & 1) * 64;
    const float4* s4 = reinterpret_cast<const float4*>(src + (size_t)(row0 + r) * DIM + kh);
#pragma unroll
    for (int q = 0; q < 16; q++) {
        float4 v = s4[q];
        int k = kh + q * 4;
        dst[(k + 0) * KSTR + r] = v.x;
        dst[(k + 1) * KSTR + r] = v.y;
        dst[(k + 2) * KSTR + r] = v.z;
        dst[(k + 3) * KSTR + r] = v.w;
    }
}

// 128x128 distance tile x TPG, 8x8 register tiling, packed f32x2 FMAs.
__global__ __launch_bounds__(256) void dist_kernel() {
    extern __shared__ __align__(16) float smem[];
    float* As = smem;                         // [128][KSTR]
    float* Bs = smem + 128 * KSTR;            // [128][KSTR]
    float* Sacc = smem + 2 * 128 * KSTR;      // [128][SPAD]
    float* jsq = Sacc + 128 * SPAD;           // [128]
    int*   jl  = (int*)(jsq + 128);           // [128]

    const int tid = threadIdx.x;
    const int tx = tid & 15, ty = tid >> 4;
    const int iBase = blockIdx.x * TILE;
    const int jg = blockIdx.y;

    for (int t = tid; t < 128 * SPAD; t += 256) Sacc[t] = 0.f;
    load_tile_t(As, g_Fp, iBase, tid);

    float isq[8];
    int gi[8];
#pragma unroll
    for (int ii = 0; ii < 8; ii++) {
        gi[ii] = iBase + ty * 8 + ii;
        isq[ii] = g_sqS[gi[ii]];
    }

    for (int t = 0; t < TPG; t++) {
        const int j0 = (jg * TPG + t) * TILE;
        __syncthreads();                       // previous tile fully consumed
        load_tile_t(Bs, g_Fp, j0, tid);
        if (tid < TILE) {
            jsq[tid] = g_sqS[j0 + tid];
            jl[tid]  = g_labS[j0 + tid];
        }
        __syncthreads();

        ull acc[32];                           // [ii][jp]
#pragma unroll
        for (int q = 0; q < 32; q++) acc[q] = 0ull;

        const float4* a4 = reinterpret_cast<const float4*>(As) + ty * 2;
        const float*  bp = Bs + tx * 8;

#pragma unroll 8
        for (int k = 0; k < DIM; k++) {
            float4 aLo = a4[k * (KSTR / 4)];
            float4 aHi = a4[k * (KSTR / 4) + 1];
            ull b0, b1, b2, b3;
            asm("ld.shared.v2.u64 {%0, %1}, [%2];"
                : "=l"(b0), "=l"(b1) : "l"(bp + k * KSTR));
            asm("ld.shared.v2.u64 {%0, %1}, [%2];"
                : "=l"(b2), "=l"(b3) : "l"(bp + k * KSTR + 4));
            ull a;
            a = dup2(aLo.x); fma2(acc[0],  a, b0); fma2(acc[1],  a, b1); fma2(acc[2],  a, b2); fma2(acc[3],  a, b3);
            a = dup2(aLo.y); fma2(acc[4],  a, b0); fma2(acc[5],  a, b1); fma2(acc[6],  a, b2); fma2(acc[7],  a, b3);
            a = dup2(aLo.z); fma2(acc[8],  a, b0); fma2(acc[9],  a, b1); fma2(acc[10], a, b2); fma2(acc[11], a, b3);
            a = dup2(aLo.w); fma2(acc[12], a, b0); fma2(acc[13], a, b1); fma2(acc[14], a, b2); fma2(acc[15], a, b3);
            a = dup2(aHi.x); fma2(acc[16], a, b0); fma2(acc[17], a, b1); fma2(acc[18], a, b2); fma2(acc[19], a, b3);
            a = dup2(aHi.y); fma2(acc[20], a, b0); fma2(acc[21], a, b1); fma2(acc[22], a, b2); fma2(acc[23], a, b3);
            a = dup2(aHi.z); fma2(acc[24], a, b0); fma2(acc[25], a, b1); fma2(acc[26], a, b2); fma2(acc[27], a, b3);
            a = dup2(aHi.w); fma2(acc[28], a, b0); fma2(acc[29], a, b1); fma2(acc[30], a, b2); fma2(acc[31], a, b3);
        }

        // epilogue: d = sqrt(isq + jsq - 2 dot); run-length segment-sum over
        // sorted labels, flush runs into Sacc via shared atomics (rare).
        const int jbase = tx * 8;
        float run[8];
#pragma unroll
        for (int ii = 0; ii < 8; ii++) run[ii] = 0.f;
        int cur = jl[jbase];
#pragma unroll
        for (int jj = 0; jj < 8; jj++) {
            const int jgl = j0 + jbase + jj;
            const int c = jl[jbase + jj];
            if (c != cur) {
#pragma unroll
                for (int ii = 0; ii < 8; ii++) {
                    atomicAdd(&Sacc[(ty * 8 + ii) * SPAD + cur], run[ii]);
                    run[ii] = 0.f;
                }
                cur = c;
            }
            const float sj = jsq[jbase + jj];
            const int jp = jj >> 1;
#pragma unroll
            for (int ii = 0; ii < 8; ii++) {
                ull a2 = acc[ii * 4 + jp];
                float dot = (jj & 1) ? __uint_as_float((unsigned)(a2 >> 32))
                                     : __uint_as_float((unsigned)(a2 & 0xffffffffull));
                float d2 = isq[ii] + sj - 2.f * dot;
                float d = 0.f;
                if (d2 > 0.f && gi[ii] != jgl)
                    asm("sqrt.approx.f32 %0, %1;" : "=f"(d) : "f"(d2));
                run[ii] += d;
            }
        }
#pragma unroll
        for (int ii = 0; ii < 8; ii++)
            atomicAdd(&Sacc[(ty * 8 + ii) * SPAD + cur], run[ii]);
    }
    __syncthreads();

    for (int idx = tid; idx < TILE * NCLUST; idx += 256) {
        int c = idx >> 7, il = idx & 127;
        g_Spart[(size_t)(jg * NCLUST + c) * N_SAMPLES + iBase + il] =
            Sacc[il * SPAD + c];
    }
}

// ---------------------------------------------------------------------------
__global__ void reduce_kernel() {
    const int t = blockIdx.x * 256 + threadIdx.x;   // t = c*8192 + i
    float s = 0.f;
#pragma unroll
    for (int g = 0; g < NGROUP; g++)
        s += g_Spart[(size_t)g * NCLUST * N_SAMPLES + t];
    g_S[t] = s;
}

__global__ void score_kernel() {
    const int i = blockIdx.x * 256 + threadIdx.x;
    __shared__ int scounts[NCLUST];
    if (threadIdx.x < NCLUST) scounts[threadIdx.x] = g_counts[threadIdx.x];
    __syncthreads();

    const int own = g_labS[i];
    float Sown = 0.f, b = FLT_MAX;
#pragma unroll
    for (int c = 0; c < NCLUST; c++) {
        float s = g_S[(size_t)c * N_SAMPLES + i];
        int cnt = scounts[c];
        if (c == own) Sown = s;
        else if (cnt > 0) b = fminf(b, s / (float)cnt);
    }
    const int ocnt = scounts[own];
    const float a = Sown / fmaxf((float)ocnt - 1.f, 1.f);
    float score = 0.f;
    if (ocnt > 1) score = (b - a) / fmaxf(b, a);

    __shared__ float red[256];
    red[threadIdx.x] = score;
    __syncthreads();
    for (int s = 128; s > 0; s >>= 1) {
        if (threadIdx.x < s) red[threadIdx.x] += red[threadIdx.x + s];
        __syncthreads();
    }
    if (threadIdx.x == 0) g_partial[blockIdx.x] = red[0];
}

__global__ void final_kernel(float* out) {
    if (threadIdx.x == 0) {
        float s = 0.f;
#pragma unroll
        for (int b = 0; b < 32; b++) s += g_partial[b];
        out[0] = s / (float)N_SAMPLES;
    }
}

// ---------------------------------------------------------------------------
extern "C" void kernel_launch(void* const* d_in, const int* in_sizes, int n_in,
                              void* d_out, int out_size) {
    const float* F = (const float*)d_in[0];
    const int* Lraw = (const int*)d_in[1];
    float* out = (float*)d_out;

    // smem: 2 tiles [128][132] + Sacc [128][65] + jsq/jl
    const int smem_bytes = (2 * 128 * KSTR + 128 * SPAD + 128) * 4 + 128 * 4;
    cudaFuncSetAttribute(dist_kernel,
                         cudaFuncAttributeMaxDynamicSharedMemorySize, smem_bytes);

    conv_labels_kernel<<<1, 256>>>(Lraw);
    sort_kernel<<<1, 256>>>();
    gather_kernel<<<N_SAMPLES / 8, 256>>>(F);
    dim3 grid(N_SAMPLES / TILE, NGROUP);
    dist_kernel<<<grid, 256, smem_bytes>>>();
    reduce_kernel<<<NCLUST * N_SAMPLES / 256, 256>>>();
    score_kernel<<<N_SAMPLES / 256, 256>>>();
    final_kernel<<<1, 32>>>(out);
}

// round 6
// speedup vs baseline: 1.2301x; 1.1020x over previous
#include <cuda_runtime.h>
#include <math.h>
#include <float.h>
#include <stdint.h>

#define N_SAMPLES 8192
#define DIM 128
#define NCLUST 64
#define TILE 128
#define NGROUP 16
#define TPG 4                     // j-tiles per block
#define KS 32                     // k-slab size
#define NSLAB (DIM / KS)          // 4
#define NU (TPG * NSLAB)          // 16 pipeline steps
#define SPAD 65

// smem offsets in floats
#define AS0 0
#define AS1 4096
#define BS0 8192
#define BS1 12288
#define SACC 16384                // 128*65 = 8320 floats
#define SMEM_FLOATS (SACC + TILE * SPAD)

// ---- device scratch ----
__device__ int   g_lab[N_SAMPLES];
__device__ int   g_labS[N_SAMPLES];
__device__ int   g_perm[N_SAMPLES];
__device__ float g_sqS[N_SAMPLES];
__device__ float g_Fp[N_SAMPLES * DIM];
__device__ int   g_counts[NCLUST];
__device__ float g_Spart[NGROUP * NCLUST * N_SAMPLES];
__device__ float g_S[NCLUST * N_SAMPLES];
__device__ float g_partial[32];

typedef unsigned long long ull;

__device__ __forceinline__ void fma2(ull& acc, ull a, ull b) {
    asm("fma.rn.f32x2 %0, %1, %2, %0;" : "+l"(acc) : "l"(a), "l"(b));
}
__device__ __forceinline__ ull dup2(float a) {
    ull r;
    asm("mov.b64 %0, {%1, %1};" : "=l"(r) : "f"(a));
    return r;
}

// ---------------------------------------------------------------------------
__global__ void conv_labels_kernel(const int* __restrict__ Lraw) {
    __shared__ int is64;
    if (threadIdx.x == 0) {
        int odd_or = 0, even_bad = 0;
        for (int k = 0; k < 256; k += 2) {
            odd_or   |= Lraw[k + 1];
            even_bad |= ((unsigned)Lraw[k] >= NCLUST);
        }
        is64 = (odd_or == 0 && !even_bad) ? 1 : 0;
    }
    __syncthreads();
    const int w = is64;
    for (int i = threadIdx.x; i < N_SAMPLES; i += blockDim.x) {
        int v = w ? Lraw[2 * i] : Lraw[i];
        g_lab[i] = min(max(v, 0), NCLUST - 1);
    }
}

// Deterministic counting sort by label: 256 segments x 32 elements.
__global__ void sort_kernel() {
    __shared__ unsigned short T[256][NCLUST];
    __shared__ int colTot[NCLUST];
    __shared__ int cbase[NCLUST];
    const int s = threadIdx.x;
#pragma unroll
    for (int c = 0; c < NCLUST; c++) T[s][c] = 0;
    const int e0 = s * 32;
    for (int e = 0; e < 32; e++) T[s][g_lab[e0 + e]]++;
    __syncthreads();
    if (s < NCLUST) {
        int tot = 0;
        for (int q = 0; q < 256; q++) tot += T[q][s];
        colTot[s] = tot;
        g_counts[s] = tot;
    }
    __syncthreads();
    if (s == 0) {
        int run = 0;
        for (int c = 0; c < NCLUST; c++) { cbase[c] = run; run += colTot[c]; }
    }
    __syncthreads();
    if (s < NCLUST) {
        int run = cbase[s];
        for (int q = 0; q < 256; q++) {
            int w = T[q][s];
            T[q][s] = (unsigned short)run;
            run += w;
        }
    }
    __syncthreads();
    for (int e = 0; e < 32; e++) {
        int idx = e0 + e;
        int c = g_lab[idx];
        int p = T[s][c]++;
        g_perm[p] = idx;
        g_labS[p] = c;
    }
}

// Gather features into sorted order + per-row sq norms. block = 8x32.
__global__ void gather_kernel(const float* __restrict__ F) {
    const int lane = threadIdx.x & 31;
    const int p = blockIdx.x * 8 + (threadIdx.x >> 5);
    const int src = g_perm[p];
    float4 v = reinterpret_cast<const float4*>(F)[src * 32 + lane];
    reinterpret_cast<float4*>(g_Fp)[p * 32 + lane] = v;
    float s = v.x * v.x + v.y * v.y + v.z * v.z + v.w * v.w;
#pragma unroll
    for (int o = 16; o > 0; o >>= 1) s += __shfl_down_sync(0xffffffffu, s, o);
    if (lane == 0) g_sqS[p] = s;
}

// ---------------------------------------------------------------------------
// dist kernel: 128x128 tile, 8x8 reg tiling, FFMA2, double-buffered 32-k slabs
__global__ __launch_bounds__(256, 2) void dist_kernel() {
    extern __shared__ __align__(16) float smem[];
    const int tid = threadIdx.x;
    const int tx = tid & 15, ty = tid >> 4;
    const int iBase = blockIdx.x * TILE;
    const int jg = blockIdx.y;

    float* Sacc = smem + SACC;
    for (int t = tid; t < TILE * SPAD; t += 256) Sacc[t] = 0.f;

    // slab staging: thread handles row r, k-quarter q (16 k values = 4 float4)
    const int r = tid & 127;
    const int q = tid >> 7;

    float4 stA[4], stB[4];
    float run[8];
    ull acc[32];

    float isq[8];
#pragma unroll
    for (int ii = 0; ii < 8; ii++) isq[ii] = g_sqS[iBase + ty * 8 + ii];

    // LDG for slab u: tile t=u>>2, slab s=u&3
#define LDG_SLAB(u, st, rowBase)                                              \
    {                                                                         \
        const float* src = g_Fp + (size_t)((rowBase) + r) * DIM +             \
                           ((u) & 3) * KS + q * 16;                           \
        _Pragma("unroll")                                                     \
        for (int m = 0; m < 4; m++)                                           \
            (st)[m] = reinterpret_cast<const float4*>(src)[m];                \
    }
#define STS_SLAB(buf, st)                                                     \
    {                                                                         \
        float* dst = smem + (buf) + q * 16 * TILE + r;                        \
        _Pragma("unroll")                                                     \
        for (int m = 0; m < 4; m++) {                                         \
            dst[(m * 4 + 0) * TILE] = (st)[m].x;                              \
            dst[(m * 4 + 1) * TILE] = (st)[m].y;                              \
            dst[(m * 4 + 2) * TILE] = (st)[m].z;                              \
            dst[(m * 4 + 3) * TILE] = (st)[m].w;                              \
        }                                                                     \
    }

    const int jtBase = jg * TPG;

    // prologue: slab 0 -> buf0; prefetch slab 1
    LDG_SLAB(0, stA, iBase);
    LDG_SLAB(0, stB, jtBase * TILE);
    STS_SLAB(AS0, stA);
    STS_SLAB(BS0, stB);
    LDG_SLAB(1, stA, iBase);
    LDG_SLAB(1, stB, jtBase * TILE);
    __syncthreads();

#pragma unroll 1
    for (int u = 0; u < NU; u++) {
        const int p = u & 1;
        if ((u & 3) == 0) {
#pragma unroll
            for (int z = 0; z < 32; z++) acc[z] = 0ull;
        }

        const float4* a4 = reinterpret_cast<const float4*>(
                               smem + (p ? AS1 : AS0)) + ty * 2;
        const float* bp = smem + (p ? BS1 : BS0) + tx * 8;
#pragma unroll 8
        for (int k = 0; k < KS; k++) {
            float4 aLo = a4[k * (TILE / 4)];
            float4 aHi = a4[k * (TILE / 4) + 1];
            ull b0, b1, b2, b3;
            asm("ld.shared.v2.u64 {%0, %1}, [%2];"
                : "=l"(b0), "=l"(b1) : "l"(bp + k * TILE));
            asm("ld.shared.v2.u64 {%0, %1}, [%2];"
                : "=l"(b2), "=l"(b3) : "l"(bp + k * TILE + 4));
            ull a;
            a = dup2(aLo.x); fma2(acc[0],  a, b0); fma2(acc[1],  a, b1); fma2(acc[2],  a, b2); fma2(acc[3],  a, b3);
            a = dup2(aLo.y); fma2(acc[4],  a, b0); fma2(acc[5],  a, b1); fma2(acc[6],  a, b2); fma2(acc[7],  a, b3);
            a = dup2(aLo.z); fma2(acc[8],  a, b0); fma2(acc[9],  a, b1); fma2(acc[10], a, b2); fma2(acc[11], a, b3);
            a = dup2(aLo.w); fma2(acc[12], a, b0); fma2(acc[13], a, b1); fma2(acc[14], a, b2); fma2(acc[15], a, b3);
            a = dup2(aHi.x); fma2(acc[16], a, b0); fma2(acc[17], a, b1); fma2(acc[18], a, b2); fma2(acc[19], a, b3);
            a = dup2(aHi.y); fma2(acc[20], a, b0); fma2(acc[21], a, b1); fma2(acc[22], a, b2); fma2(acc[23], a, b3);
            a = dup2(aHi.z); fma2(acc[24], a, b0); fma2(acc[25], a, b1); fma2(acc[26], a, b2); fma2(acc[27], a, b3);
            a = dup2(aHi.w); fma2(acc[28], a, b0); fma2(acc[29], a, b1); fma2(acc[30], a, b2); fma2(acc[31], a, b3);
        }

        // stage next slab into the other buffer; prefetch one further ahead
        if (u + 1 < NU) {
            const int nb = (u + 1) & 1;
            STS_SLAB(nb ? AS1 : AS0, stA);
            STS_SLAB(nb ? BS1 : BS0, stB);
            if (u + 2 < NU) {
                const int t2 = (u + 2) >> 2;
                LDG_SLAB(u + 2, stA, iBase);
                LDG_SLAB(u + 2, stB, (jtBase + t2) * TILE);
            }
        }

        // tile epilogue after last slab of each tile
        if ((u & 3) == 3) {
            const int t = u >> 2;
            const int j0 = (jtBase + t) * TILE;
            const int jbase = tx * 8;
            int   jlr[8];
            float jsr[8];
#pragma unroll
            for (int jj = 0; jj < 8; jj++) {
                jlr[jj] = g_labS[j0 + jbase + jj];
                jsr[jj] = g_sqS[j0 + jbase + jj];
            }
#pragma unroll
            for (int ii = 0; ii < 8; ii++) run[ii] = 0.f;
            int cur = jlr[0];
#pragma unroll
            for (int jj = 0; jj < 8; jj++) {
                const int jgl = j0 + jbase + jj;
                const int c = jlr[jj];
                if (c != cur) {
#pragma unroll
                    for (int ii = 0; ii < 8; ii++) {
                        atomicAdd(&Sacc[(ty * 8 + ii) * SPAD + cur], run[ii]);
                        run[ii] = 0.f;
                    }
                    cur = c;
                }
                const float sj = jsr[jj];
                const int jp = jj >> 1;
#pragma unroll
                for (int ii = 0; ii < 8; ii++) {
                    ull a2 = acc[ii * 4 + jp];
                    float dot = (jj & 1) ? __uint_as_float((unsigned)(a2 >> 32))
                                         : __uint_as_float((unsigned)(a2 & 0xffffffffull));
                    float d2 = isq[ii] + sj - 2.f * dot;
                    float d = 0.f;
                    if (d2 > 0.f && (iBase + ty * 8 + ii) != jgl)
                        asm("sqrt.approx.f32 %0, %1;" : "=f"(d) : "f"(d2));
                    run[ii] += d;
                }
            }
#pragma unroll
            for (int ii = 0; ii < 8; ii++)
                atomicAdd(&Sacc[(ty * 8 + ii) * SPAD + cur], run[ii]);
        }
        __syncthreads();
    }

    for (int idx = tid; idx < TILE * NCLUST; idx += 256) {
        int c = idx >> 7, il = idx & 127;
        g_Spart[(size_t)(jg * NCLUST + c) * N_SAMPLES + iBase + il] =
            Sacc[il * SPAD + c];
    }
#undef LDG_SLAB
#undef STS_SLAB
}

// ---------------------------------------------------------------------------
__global__ void reduce_kernel() {
    const int t = blockIdx.x * 256 + threadIdx.x;
    float s = 0.f;
#pragma unroll
    for (int g = 0; g < NGROUP; g++)
        s += g_Spart[(size_t)g * NCLUST * N_SAMPLES + t];
    g_S[t] = s;
}

__global__ void score_kernel() {
    const int i = blockIdx.x * 256 + threadIdx.x;
    __shared__ int scounts[NCLUST];
    if (threadIdx.x < NCLUST) scounts[threadIdx.x] = g_counts[threadIdx.x];
    __syncthreads();

    const int own = g_labS[i];
    float Sown = 0.f, b = FLT_MAX;
#pragma unroll
    for (int c = 0; c < NCLUST; c++) {
        float s = g_S[(size_t)c * N_SAMPLES + i];
        int cnt = scounts[c];
        if (c == own) Sown = s;
        else if (cnt > 0) b = fminf(b, s / (float)cnt);
    }
    const int ocnt = scounts[own];
    const float a = Sown / fmaxf((float)ocnt - 1.f, 1.f);
    float score = 0.f;
    if (ocnt > 1) score = (b - a) / fmaxf(b, a);

    __shared__ float red[256];
    red[threadIdx.x] = score;
    __syncthreads();
    for (int s = 128; s > 0; s >>= 1) {
        if (threadIdx.x < s) red[threadIdx.x] += red[threadIdx.x + s];
        __syncthreads();
    }
    if (threadIdx.x == 0) g_partial[blockIdx.x] = red[0];
}

__global__ void final_kernel(float* out) {
    if (threadIdx.x == 0) {
        float s = 0.f;
#pragma unroll
        for (int b = 0; b < 32; b++) s += g_partial[b];
        out[0] = s / (float)N_SAMPLES;
    }
}

// ---------------------------------------------------------------------------
extern "C" void kernel_launch(void* const* d_in, const int* in_sizes, int n_in,
                              void* d_out, int out_size) {
    const float* F = (const float*)d_in[0];
    const int* Lraw = (const int*)d_in[1];
    float* out = (float*)d_out;

    const int smem_bytes = SMEM_FLOATS * 4;   // ~98.8 KB -> 2 CTAs/SM
    cudaFuncSetAttribute(dist_kernel,
                         cudaFuncAttributeMaxDynamicSharedMemorySize, smem_bytes);

    conv_labels_kernel<<<1, 256>>>(Lraw);
    sort_kernel<<<1, 256>>>();
    gather_kernel<<<N_SAMPLES / 8, 256>>>(F);
    dim3 grid(N_SAMPLES / TILE, NGROUP);
    dist_kernel<<<grid, 256, smem_bytes>>>();
    reduce_kernel<<<NCLUST * N_SAMPLES / 256, 256>>>();
    score_kernel<<<N_SAMPLES / 256, 256>>>();
    final_kernel<<<1, 32>>>(out);
}

// round 7
// speedup vs baseline: 1.6123x; 1.3107x over previous
#include <cuda_runtime.h>
#include <math.h>
#include <float.h>
#include <stdint.h>

#define N_SAMPLES 8192
#define DIM 128
#define NCLUST 64
#define TILE 128
#define NGROUP 16
#define TPG 4                     // j-tiles per block
#define KS 32                     // k-slab size
#define NSLAB (DIM / KS)          // 4
#define NU (TPG * NSLAB)          // 16 pipeline steps
#define SPAD 65

// smem offsets in floats (each slab buffer = KS*TILE = 4096 floats = 16KB)
#define AS0 0
#define AS1 4096
#define BS0 8192
#define BS1 12288
#define SACC 16384                // 128*65 = 8320 floats
#define SMEM_FLOATS (SACC + TILE * SPAD)

// ---- device scratch ----
__device__ int   g_lab[N_SAMPLES];
__device__ int   g_labS[N_SAMPLES];
__device__ int   g_perm[N_SAMPLES];
__device__ float g_sqS[N_SAMPLES];
__device__ float g_Fp[N_SAMPLES * DIM];     // sorted, row-major
__device__ float g_FpT[DIM * N_SAMPLES];    // sorted, k-major
__device__ int   g_counts[NCLUST];
__device__ float g_Spart[NGROUP * NCLUST * N_SAMPLES];
__device__ float g_S[NCLUST * N_SAMPLES];
__device__ float g_partial[32];

typedef unsigned long long ull;

__device__ __forceinline__ void fma2(ull& acc, ull a, ull b) {
    asm("fma.rn.f32x2 %0, %1, %2, %0;" : "+l"(acc) : "l"(a), "l"(b));
}
__device__ __forceinline__ ull dup2(float a) {
    ull r;
    asm("mov.b64 %0, {%1, %1};" : "=l"(r) : "f"(a));
    return r;
}
__device__ __forceinline__ uint32_t smem_u32(const void* p) {
    uint32_t a;
    asm("{ .reg .u64 t; cvta.to.shared.u64 t, %1; cvt.u32.u64 %0, t; }"
        : "=r"(a) : "l"(p));
    return a;
}
__device__ __forceinline__ void cp16(uint32_t dst, const void* src) {
    asm volatile("cp.async.cg.shared.global [%0], [%1], 16;"
                 :: "r"(dst), "l"(src) : "memory");
}
#define CP_COMMIT() asm volatile("cp.async.commit_group;" ::: "memory")
#define CP_WAIT1()  asm volatile("cp.async.wait_group 1;" ::: "memory")
#define CP_WAIT0()  asm volatile("cp.async.wait_group 0;" ::: "memory")

// ---------------------------------------------------------------------------
__global__ void conv_labels_kernel(const int* __restrict__ Lraw) {
    __shared__ int is64;
    if (threadIdx.x == 0) {
        int odd_or = 0, even_bad = 0;
        for (int k = 0; k < 256; k += 2) {
            odd_or   |= Lraw[k + 1];
            even_bad |= ((unsigned)Lraw[k] >= NCLUST);
        }
        is64 = (odd_or == 0 && !even_bad) ? 1 : 0;
    }
    __syncthreads();
    const int w = is64;
    for (int i = threadIdx.x; i < N_SAMPLES; i += blockDim.x) {
        int v = w ? Lraw[2 * i] : Lraw[i];
        g_lab[i] = min(max(v, 0), NCLUST - 1);
    }
}

// Deterministic counting sort by label: 256 segments x 32 elements.
__global__ void sort_kernel() {
    __shared__ unsigned short T[256][NCLUST];
    __shared__ int colTot[NCLUST];
    __shared__ int cbase[NCLUST];
    const int s = threadIdx.x;
#pragma unroll
    for (int c = 0; c < NCLUST; c++) T[s][c] = 0;
    const int e0 = s * 32;
    for (int e = 0; e < 32; e++) T[s][g_lab[e0 + e]]++;
    __syncthreads();
    if (s < NCLUST) {
        int tot = 0;
        for (int q = 0; q < 256; q++) tot += T[q][s];
        colTot[s] = tot;
        g_counts[s] = tot;
    }
    __syncthreads();
    if (s == 0) {
        int run = 0;
        for (int c = 0; c < NCLUST; c++) { cbase[c] = run; run += colTot[c]; }
    }
    __syncthreads();
    if (s < NCLUST) {
        int run = cbase[s];
        for (int q = 0; q < 256; q++) {
            int w = T[q][s];
            T[q][s] = (unsigned short)run;
            run += w;
        }
    }
    __syncthreads();
    for (int e = 0; e < 32; e++) {
        int idx = e0 + e;
        int c = g_lab[idx];
        int p = T[s][c]++;
        g_perm[p] = idx;
        g_labS[p] = c;
    }
}

// Gather features into sorted row-major order + per-row sq norms. block = 8x32.
__global__ void gather_kernel(const float* __restrict__ F) {
    const int lane = threadIdx.x & 31;
    const int p = blockIdx.x * 8 + (threadIdx.x >> 5);
    const int src = g_perm[p];
    float4 v = reinterpret_cast<const float4*>(F)[src * 32 + lane];
    reinterpret_cast<float4*>(g_Fp)[p * 32 + lane] = v;
    float s = v.x * v.x + v.y * v.y + v.z * v.z + v.w * v.w;
#pragma unroll
    for (int o = 16; o > 0; o >>= 1) s += __shfl_down_sync(0xffffffffu, s, o);
    if (lane == 0) g_sqS[p] = s;
}

// 32x32 smem transpose: g_Fp[row][k] -> g_FpT[k][row]
__global__ void transpose_kernel() {
    __shared__ float t[32][33];
    const int bi = blockIdx.x * 32;     // row block
    const int bk = blockIdx.y * 32;     // k block
    const int x = threadIdx.x, y = threadIdx.y;
#pragma unroll
    for (int m = 0; m < 32; m += 8)
        t[y + m][x] = g_Fp[(size_t)(bi + y + m) * DIM + bk + x];
    __syncthreads();
#pragma unroll
    for (int m = 0; m < 32; m += 8)
        g_FpT[(size_t)(bk + y + m) * N_SAMPLES + bi + x] = t[x][y + m];
}

// ---------------------------------------------------------------------------
// dist: 128x128 tiles, 8x8 reg tiling, FFMA2; slabs staged with cp.async
// from the k-major copy (contiguous -> no transpose, no staging registers).
__global__ __launch_bounds__(256, 2) void dist_kernel() {
    extern __shared__ __align__(16) float smem[];
    const uint32_t sb = smem_u32(smem);
    const int tid = threadIdx.x;
    const int tx = tid & 15, ty = tid >> 4;
    const int iBase = blockIdx.x * TILE;
    const int jg = blockIdx.y;
    const int jtBase = jg * TPG;

    float* Sacc = smem + SACC;
    for (int t = tid; t < TILE * SPAD; t += 256) Sacc[t] = 0.f;

    // slab issue: 1024 16B-chunks per slab (A+B) -> 4 per thread each
    // chunk c (0..1023): k = c>>5, off16 = c&31
#define ISSUE_SLAB(u)                                                         \
    {                                                                         \
        const int _s = (u) & 3;                                               \
        const int _t = (u) >> 2;                                              \
        const int _b = (u) & 1;                                               \
        const float* srcA = g_FpT + (size_t)(_s * KS) * N_SAMPLES + iBase;    \
        const float* srcB = g_FpT + (size_t)(_s * KS) * N_SAMPLES +           \
                            (jtBase + _t) * TILE;                             \
        const uint32_t dA = sb + (_b ? AS1 : AS0) * 4;                        \
        const uint32_t dB = sb + (_b ? BS1 : BS0) * 4;                        \
        _Pragma("unroll")                                                     \
        for (int r = 0; r < 4; r++) {                                         \
            int c = tid + r * 256;                                            \
            int kk = c >> 5, off = (c & 31) * 4;                              \
            cp16(dA + (uint32_t)(kk * TILE + off) * 4,                        \
                 srcA + (size_t)kk * N_SAMPLES + off);                        \
            cp16(dB + (uint32_t)(kk * TILE + off) * 4,                        \
                 srcB + (size_t)kk * N_SAMPLES + off);                        \
        }                                                                     \
        CP_COMMIT();                                                          \
    }

    float isq[8];
#pragma unroll
    for (int ii = 0; ii < 8; ii++) isq[ii] = g_sqS[iBase + ty * 8 + ii];

    ull acc[32];
    float run[8];

    ISSUE_SLAB(0);
    ISSUE_SLAB(1);
    CP_WAIT1();
    __syncthreads();

#pragma unroll 1
    for (int u = 0; u < NU; u++) {
        const int p = u & 1;
        if ((u & 3) == 0) {
#pragma unroll
            for (int z = 0; z < 32; z++) acc[z] = 0ull;
        }

        const float* Ab = smem + (p ? AS1 : AS0);
        const float* bp = smem + (p ? BS1 : BS0) + tx * 8;
#pragma unroll 8
        for (int k = 0; k < KS; k++) {
            float4 aLo = *reinterpret_cast<const float4*>(Ab + k * TILE + ty * 8);
            float4 aHi = *reinterpret_cast<const float4*>(Ab + k * TILE + ty * 8 + 4);
            ull b0, b1, b2, b3;
            asm("ld.shared.v2.u64 {%0, %1}, [%2];"
                : "=l"(b0), "=l"(b1) : "l"(bp + k * TILE));
            asm("ld.shared.v2.u64 {%0, %1}, [%2];"
                : "=l"(b2), "=l"(b3) : "l"(bp + k * TILE + 4));
            ull a;
            a = dup2(aLo.x); fma2(acc[0],  a, b0); fma2(acc[1],  a, b1); fma2(acc[2],  a, b2); fma2(acc[3],  a, b3);
            a = dup2(aLo.y); fma2(acc[4],  a, b0); fma2(acc[5],  a, b1); fma2(acc[6],  a, b2); fma2(acc[7],  a, b3);
            a = dup2(aLo.z); fma2(acc[8],  a, b0); fma2(acc[9],  a, b1); fma2(acc[10], a, b2); fma2(acc[11], a, b3);
            a = dup2(aLo.w); fma2(acc[12], a, b0); fma2(acc[13], a, b1); fma2(acc[14], a, b2); fma2(acc[15], a, b3);
            a = dup2(aHi.x); fma2(acc[16], a, b0); fma2(acc[17], a, b1); fma2(acc[18], a, b2); fma2(acc[19], a, b3);
            a = dup2(aHi.y); fma2(acc[20], a, b0); fma2(acc[21], a, b1); fma2(acc[22], a, b2); fma2(acc[23], a, b3);
            a = dup2(aHi.z); fma2(acc[24], a, b0); fma2(acc[25], a, b1); fma2(acc[26], a, b2); fma2(acc[27], a, b3);
            a = dup2(aHi.w); fma2(acc[28], a, b0); fma2(acc[29], a, b1); fma2(acc[30], a, b2); fma2(acc[31], a, b3);
        }

        // tile epilogue after last slab of each tile
        if ((u & 3) == 3) {
            const int t = u >> 2;
            const int j0 = (jtBase + t) * TILE;
            const int jbase = tx * 8;
            int   jlr[8];
            float jsr[8];
#pragma unroll
            for (int jj = 0; jj < 8; jj++) {
                jlr[jj] = g_labS[j0 + jbase + jj];
                jsr[jj] = g_sqS[j0 + jbase + jj];
            }
#pragma unroll
            for (int ii = 0; ii < 8; ii++) run[ii] = 0.f;
            int cur = jlr[0];
#pragma unroll
            for (int jj = 0; jj < 8; jj++) {
                const int jgl = j0 + jbase + jj;
                const int c = jlr[jj];
                if (c != cur) {
#pragma unroll
                    for (int ii = 0; ii < 8; ii++) {
                        atomicAdd(&Sacc[(ty * 8 + ii) * SPAD + cur], run[ii]);
                        run[ii] = 0.f;
                    }
                    cur = c;
                }
                const float sj = jsr[jj];
                const int jp = jj >> 1;
#pragma unroll
                for (int ii = 0; ii < 8; ii++) {
                    ull a2 = acc[ii * 4 + jp];
                    float dot = (jj & 1) ? __uint_as_float((unsigned)(a2 >> 32))
                                         : __uint_as_float((unsigned)(a2 & 0xffffffffull));
                    float d2 = isq[ii] + sj - 2.f * dot;
                    float d = 0.f;
                    if (d2 > 0.f && (iBase + ty * 8 + ii) != jgl)
                        asm("sqrt.approx.f32 %0, %1;" : "=f"(d) : "f"(d2));
                    run[ii] += d;
                }
            }
#pragma unroll
            for (int ii = 0; ii < 8; ii++)
                atomicAdd(&Sacc[(ty * 8 + ii) * SPAD + cur], run[ii]);
        }

        __syncthreads();                 // everyone done reading buf p
        if (u + 2 < NU) ISSUE_SLAB(u + 2);
        CP_WAIT1();                      // buf for u+1 is complete
        __syncthreads();
    }

    for (int idx = tid; idx < TILE * NCLUST; idx += 256) {
        int c = idx >> 7, il = idx & 127;
        g_Spart[(size_t)(jg * NCLUST + c) * N_SAMPLES + iBase + il] =
            Sacc[il * SPAD + c];
    }
#undef ISSUE_SLAB
}

// ---------------------------------------------------------------------------
__global__ void reduce_kernel() {
    const int t = blockIdx.x * 256 + threadIdx.x;
    float s = 0.f;
#pragma unroll
    for (int g = 0; g < NGROUP; g++)
        s += g_Spart[(size_t)g * NCLUST * N_SAMPLES + t];
    g_S[t] = s;
}

__global__ void score_kernel() {
    const int i = blockIdx.x * 256 + threadIdx.x;
    __shared__ int scounts[NCLUST];
    if (threadIdx.x < NCLUST) scounts[threadIdx.x] = g_counts[threadIdx.x];
    __syncthreads();

    const int own = g_labS[i];
    float Sown = 0.f, b = FLT_MAX;
#pragma unroll
    for (int c = 0; c < NCLUST; c++) {
        float s = g_S[(size_t)c * N_SAMPLES + i];
        int cnt = scounts[c];
        if (c == own) Sown = s;
        else if (cnt > 0) b = fminf(b, s / (float)cnt);
    }
    const int ocnt = scounts[own];
    const float a = Sown / fmaxf((float)ocnt - 1.f, 1.f);
    float score = 0.f;
    if (ocnt > 1) score = (b - a) / fmaxf(b, a);

    __shared__ float red[256];
    red[threadIdx.x] = score;
    __syncthreads();
    for (int s = 128; s > 0; s >>= 1) {
        if (threadIdx.x < s) red[threadIdx.x] += red[threadIdx.x + s];
        __syncthreads();
    }
    if (threadIdx.x == 0) g_partial[blockIdx.x] = red[0];
}

__global__ void final_kernel(float* out) {
    if (threadIdx.x == 0) {
        float s = 0.f;
#pragma unroll
        for (int b = 0; b < 32; b++) s += g_partial[b];
        out[0] = s / (float)N_SAMPLES;
    }
}

// ---------------------------------------------------------------------------
extern "C" void kernel_launch(void* const* d_in, const int* in_sizes, int n_in,
                              void* d_out, int out_size) {
    const float* F = (const float*)d_in[0];
    const int* Lraw = (const int*)d_in[1];
    float* out = (float*)d_out;

    const int smem_bytes = SMEM_FLOATS * 4;   // ~98.8 KB -> 2 CTAs/SM
    cudaFuncSetAttribute(dist_kernel,
                         cudaFuncAttributeMaxDynamicSharedMemorySize, smem_bytes);

    conv_labels_kernel<<<1, 256>>>(Lraw);
    sort_kernel<<<1, 256>>>();
    gather_kernel<<<N_SAMPLES / 8, 256>>>(F);
    dim3 tgrid(N_SAMPLES / 32, DIM / 32);
    transpose_kernel<<<tgrid, dim3(32, 8)>>>();
    dim3 grid(N_SAMPLES / TILE, NGROUP);
    dist_kernel<<<grid, 256, smem_bytes>>>();
    reduce_kernel<<<NCLUST * N_SAMPLES / 256, 256>>>();
    score_kernel<<<N_SAMPLES / 256, 256>>>();
    final_kernel<<<1, 32>>>(out);
}

// round 8
// speedup vs baseline: 2.3141x; 1.4353x over previous
#include <cuda_runtime.h>
#include <math.h>
#include <float.h>
#include <stdint.h>

#define N_SAMPLES 8192
#define DIM 128
#define NCLUST 64
#define TILE 128
#define NTILES (N_SAMPLES / TILE)   // 64
#define KS 16                       // k-slab size
#define NSLAB (DIM / KS)            // 8
#define SPAD 65

// smem offsets in floats (slab buffer = KS*TILE = 2048 floats = 8KB)
#define AS0 0
#define AS1 2048
#define BS0 4096
#define BS1 6144
#define SACCI 8192                  // 128*65
#define SACCJ (SACCI + TILE * SPAD)
#define SMEM_FLOATS (SACCJ + TILE * SPAD)   // 24832 floats = 97KB

// ---- device scratch ----
__device__ int   g_lab[N_SAMPLES];
__device__ int   g_labS[N_SAMPLES];
__device__ int   g_perm[N_SAMPLES];
__device__ float g_sqS[N_SAMPLES];
__device__ float g_Fp[N_SAMPLES * DIM];
__device__ float g_FpT[DIM * N_SAMPLES];
__device__ int   g_counts[NCLUST];
// [partner_tile][cluster][row] -- each slot written by exactly one CTA
__device__ float g_Spart[NTILES * NCLUST * N_SAMPLES];
__device__ float g_S[NCLUST * N_SAMPLES];
__device__ float g_partial[32];

typedef unsigned long long ull;

__device__ __forceinline__ void fma2(ull& acc, ull a, ull b) {
    asm("fma.rn.f32x2 %0, %1, %2, %0;" : "+l"(acc) : "l"(a), "l"(b));
}
__device__ __forceinline__ ull dup2(float a) {
    ull r;
    asm("mov.b64 %0, {%1, %1};" : "=l"(r) : "f"(a));
    return r;
}
__device__ __forceinline__ uint32_t smem_u32(const void* p) {
    uint32_t a;
    asm("{ .reg .u64 t; cvta.to.shared.u64 t, %1; cvt.u32.u64 %0, t; }"
        : "=r"(a) : "l"(p));
    return a;
}
__device__ __forceinline__ void cp16(uint32_t dst, const void* src) {
    asm volatile("cp.async.cg.shared.global [%0], [%1], 16;"
                 :: "r"(dst), "l"(src) : "memory");
}
#define CP_COMMIT() asm volatile("cp.async.commit_group;" ::: "memory")
#define CP_WAIT1()  asm volatile("cp.async.wait_group 1;" ::: "memory")
#define CP_WAIT0()  asm volatile("cp.async.wait_group 0;" ::: "memory")

// ---------------------------------------------------------------------------
__global__ void conv_labels_kernel(const int* __restrict__ Lraw) {
    __shared__ int is64;
    if (threadIdx.x == 0) {
        int odd_or = 0, even_bad = 0;
        for (int k = 0; k < 256; k += 2) {
            odd_or   |= Lraw[k + 1];
            even_bad |= ((unsigned)Lraw[k] >= NCLUST);
        }
        is64 = (odd_or == 0 && !even_bad) ? 1 : 0;
    }
    __syncthreads();
    const int w = is64;
    for (int i = threadIdx.x; i < N_SAMPLES; i += blockDim.x) {
        int v = w ? Lraw[2 * i] : Lraw[i];
        g_lab[i] = min(max(v, 0), NCLUST - 1);
    }
}

// Deterministic counting sort by label: 256 segments x 32 elements.
__global__ void sort_kernel() {
    __shared__ unsigned short T[256][NCLUST];
    __shared__ int colTot[NCLUST];
    __shared__ int cbase[NCLUST];
    const int s = threadIdx.x;
#pragma unroll
    for (int c = 0; c < NCLUST; c++) T[s][c] = 0;
    const int e0 = s * 32;
    for (int e = 0; e < 32; e++) T[s][g_lab[e0 + e]]++;
    __syncthreads();
    if (s < NCLUST) {
        int tot = 0;
        for (int q = 0; q < 256; q++) tot += T[q][s];
        colTot[s] = tot;
        g_counts[s] = tot;
    }
    __syncthreads();
    if (s == 0) {
        int run = 0;
        for (int c = 0; c < NCLUST; c++) { cbase[c] = run; run += colTot[c]; }
    }
    __syncthreads();
    if (s < NCLUST) {
        int run = cbase[s];
        for (int q = 0; q < 256; q++) {
            int w = T[q][s];
            T[q][s] = (unsigned short)run;
            run += w;
        }
    }
    __syncthreads();
    for (int e = 0; e < 32; e++) {
        int idx = e0 + e;
        int c = g_lab[idx];
        int p = T[s][c]++;
        g_perm[p] = idx;
        g_labS[p] = c;
    }
}

// Gather features into sorted order + per-row sq norms. block = 8x32.
__global__ void gather_kernel(const float* __restrict__ F) {
    const int lane = threadIdx.x & 31;
    const int p = blockIdx.x * 8 + (threadIdx.x >> 5);
    const int src = g_perm[p];
    float4 v = reinterpret_cast<const float4*>(F)[src * 32 + lane];
    reinterpret_cast<float4*>(g_Fp)[p * 32 + lane] = v;
    float s = v.x * v.x + v.y * v.y + v.z * v.z + v.w * v.w;
#pragma unroll
    for (int o = 16; o > 0; o >>= 1) s += __shfl_down_sync(0xffffffffu, s, o);
    if (lane == 0) g_sqS[p] = s;
}

// 32x32 smem transpose: g_Fp[row][k] -> g_FpT[k][row]
__global__ void transpose_kernel() {
    __shared__ float t[32][33];
    const int bi = blockIdx.x * 32;
    const int bk = blockIdx.y * 32;
    const int x = threadIdx.x, y = threadIdx.y;
#pragma unroll
    for (int m = 0; m < 32; m += 8)
        t[y + m][x] = g_Fp[(size_t)(bi + y + m) * DIM + bk + x];
    __syncthreads();
#pragma unroll
    for (int m = 0; m < 32; m += 8)
        g_FpT[(size_t)(bk + y + m) * N_SAMPLES + bi + x] = t[x][y + m];
}

// ---------------------------------------------------------------------------
// dist: one 128x128 tile per CTA, only jt >= it (symmetry). 8x8 reg tiling,
// FFMA2, cp.async double-buffered 16-k slabs. Off-diag tiles accumulate both
// i-side (SaccI) and j-side (SaccJ) segment sums.
__global__ __launch_bounds__(256, 2) void dist_kernel() {
    const int it = blockIdx.x;
    const int jt = blockIdx.y;
    if (jt < it) return;
    const bool diag = (it == jt);

    extern __shared__ __align__(16) float smem[];
    const uint32_t sb = smem_u32(smem);
    const int tid = threadIdx.x;
    const int tx = tid & 15, ty = tid >> 4;
    const int iBase = it * TILE;
    const int jBase = jt * TILE;

    for (int t = tid; t < 2 * TILE * SPAD; t += 256) smem[SACCI + t] = 0.f;

    // slab issue: 512 16B-chunks per matrix -> 2 per thread each
#define ISSUE_SLAB(u)                                                         \
    {                                                                         \
        const int _b = (u) & 1;                                               \
        const float* srcA = g_FpT + (size_t)((u) * KS) * N_SAMPLES + iBase;   \
        const float* srcB = g_FpT + (size_t)((u) * KS) * N_SAMPLES + jBase;   \
        const uint32_t dA = sb + (_b ? AS1 : AS0) * 4;                        \
        const uint32_t dB = sb + (_b ? BS1 : BS0) * 4;                        \
        _Pragma("unroll")                                                     \
        for (int rr = 0; rr < 2; rr++) {                                      \
            int c = tid + rr * 256;                                           \
            int kk = c >> 5, off = (c & 31) * 4;                              \
            cp16(dA + (uint32_t)(kk * TILE + off) * 4,                        \
                 srcA + (size_t)kk * N_SAMPLES + off);                        \
            cp16(dB + (uint32_t)(kk * TILE + off) * 4,                        \
                 srcB + (size_t)kk * N_SAMPLES + off);                        \
        }                                                                     \
        CP_COMMIT();                                                          \
    }

    float isq[8];
#pragma unroll
    for (int ii = 0; ii < 8; ii++) isq[ii] = g_sqS[iBase + ty * 8 + ii];

    ull acc[32];
#pragma unroll
    for (int z = 0; z < 32; z++) acc[z] = 0ull;

    ISSUE_SLAB(0);
    ISSUE_SLAB(1);
    CP_WAIT1();
    __syncthreads();

#pragma unroll 1
    for (int u = 0; u < NSLAB; u++) {
        const int p = u & 1;
        const float* Ab = smem + (p ? AS1 : AS0);
        const float* bp = smem + (p ? BS1 : BS0) + tx * 8;
#pragma unroll
        for (int k = 0; k < KS; k++) {
            float4 aLo = *reinterpret_cast<const float4*>(Ab + k * TILE + ty * 8);
            float4 aHi = *reinterpret_cast<const float4*>(Ab + k * TILE + ty * 8 + 4);
            ull b0, b1, b2, b3;
            asm("ld.shared.v2.u64 {%0, %1}, [%2];"
                : "=l"(b0), "=l"(b1) : "l"(bp + k * TILE));
            asm("ld.shared.v2.u64 {%0, %1}, [%2];"
                : "=l"(b2), "=l"(b3) : "l"(bp + k * TILE + 4));
            ull a;
            a = dup2(aLo.x); fma2(acc[0],  a, b0); fma2(acc[1],  a, b1); fma2(acc[2],  a, b2); fma2(acc[3],  a, b3);
            a = dup2(aLo.y); fma2(acc[4],  a, b0); fma2(acc[5],  a, b1); fma2(acc[6],  a, b2); fma2(acc[7],  a, b3);
            a = dup2(aLo.z); fma2(acc[8],  a, b0); fma2(acc[9],  a, b1); fma2(acc[10], a, b2); fma2(acc[11], a, b3);
            a = dup2(aLo.w); fma2(acc[12], a, b0); fma2(acc[13], a, b1); fma2(acc[14], a, b2); fma2(acc[15], a, b3);
            a = dup2(aHi.x); fma2(acc[16], a, b0); fma2(acc[17], a, b1); fma2(acc[18], a, b2); fma2(acc[19], a, b3);
            a = dup2(aHi.y); fma2(acc[20], a, b0); fma2(acc[21], a, b1); fma2(acc[22], a, b2); fma2(acc[23], a, b3);
            a = dup2(aHi.z); fma2(acc[24], a, b0); fma2(acc[25], a, b1); fma2(acc[26], a, b2); fma2(acc[27], a, b3);
            a = dup2(aHi.w); fma2(acc[28], a, b0); fma2(acc[29], a, b1); fma2(acc[30], a, b2); fma2(acc[31], a, b3);
        }
        __syncthreads();
        if (u + 2 < NSLAB) {
            ISSUE_SLAB(u + 2);
            CP_WAIT1();
        } else {
            CP_WAIT0();
        }
        __syncthreads();
    }
#undef ISSUE_SLAB

    // ---- epilogue ----
    const int jbase = tx * 8;
    int   jlr[8], ilr[8];
    float jsr[8];
#pragma unroll
    for (int jj = 0; jj < 8; jj++) {
        jlr[jj] = g_labS[jBase + jbase + jj];
        jsr[jj] = g_sqS[jBase + jbase + jj];
        ilr[jj] = g_labS[iBase + ty * 8 + jj];
    }

    // convert dots -> distances in place (packed)
#pragma unroll
    for (int q = 0; q < 32; q++) {
        const int ii = q >> 2, jp = q & 3;
        ull a2 = acc[q];
        float lo = __uint_as_float((unsigned)(a2 & 0xffffffffull));
        float hi = __uint_as_float((unsigned)(a2 >> 32));
        float d2lo = isq[ii] + jsr[2 * jp]     - 2.f * lo;
        float d2hi = isq[ii] + jsr[2 * jp + 1] - 2.f * hi;
        float dlo = 0.f, dhi = 0.f;
        const int gi = iBase + ty * 8 + ii;
        if (d2lo > 0.f && gi != (jBase + jbase + 2 * jp))
            asm("sqrt.approx.f32 %0, %1;" : "=f"(dlo) : "f"(d2lo));
        if (d2hi > 0.f && gi != (jBase + jbase + 2 * jp + 1))
            asm("sqrt.approx.f32 %0, %1;" : "=f"(dhi) : "f"(d2hi));
        asm("mov.b64 %0, {%1, %2};" : "=l"(acc[q]) : "f"(dlo), "f"(dhi));
    }

    float* SaccI = smem + SACCI;
    float* SaccJ = smem + SACCJ;

    // i-side: run-length over sorted j-labels
    {
        float run[8];
#pragma unroll
        for (int ii = 0; ii < 8; ii++) run[ii] = 0.f;
        int cur = jlr[0];
#pragma unroll
        for (int jj = 0; jj < 8; jj++) {
            const int c = jlr[jj];
            if (c != cur) {
#pragma unroll
                for (int ii = 0; ii < 8; ii++) {
                    atomicAdd(&SaccI[(ty * 8 + ii) * SPAD + cur], run[ii]);
                    run[ii] = 0.f;
                }
                cur = c;
            }
            const int jp = jj >> 1;
#pragma unroll
            for (int ii = 0; ii < 8; ii++) {
                ull a2 = acc[ii * 4 + jp];
                float d = (jj & 1) ? __uint_as_float((unsigned)(a2 >> 32))
                                   : __uint_as_float((unsigned)(a2 & 0xffffffffull));
                run[ii] += d;
            }
        }
#pragma unroll
        for (int ii = 0; ii < 8; ii++)
            atomicAdd(&SaccI[(ty * 8 + ii) * SPAD + cur], run[ii]);
    }

    // j-side (off-diag only): run-length over sorted i-labels
    if (!diag) {
        float run[8];
#pragma unroll
        for (int jj = 0; jj < 8; jj++) run[jj] = 0.f;
        int cur = ilr[0];
#pragma unroll
        for (int ii = 0; ii < 8; ii++) {
            const int c = ilr[ii];
            if (c != cur) {
#pragma unroll
                for (int jj = 0; jj < 8; jj++) {
                    atomicAdd(&SaccJ[(jbase + jj) * SPAD + cur], run[jj]);
                    run[jj] = 0.f;
                }
                cur = c;
            }
#pragma unroll
            for (int jj = 0; jj < 8; jj++) {
                ull a2 = acc[ii * 4 + (jj >> 1)];
                float d = (jj & 1) ? __uint_as_float((unsigned)(a2 >> 32))
                                   : __uint_as_float((unsigned)(a2 & 0xffffffffull));
                run[jj] += d;
            }
        }
#pragma unroll
        for (int jj = 0; jj < 8; jj++)
            atomicAdd(&SaccJ[(jbase + jj) * SPAD + cur], run[jj]);
    }
    __syncthreads();

    // write partials: SaccI -> slot[jt] rows of it; SaccJ -> slot[it] rows of jt
    for (int idx = tid; idx < TILE * NCLUST; idx += 256) {
        int c = idx >> 7, il = idx & 127;
        g_Spart[(size_t)(jt * NCLUST + c) * N_SAMPLES + iBase + il] =
            SaccI[il * SPAD + c];
    }
    if (!diag) {
        for (int idx = tid; idx < TILE * NCLUST; idx += 256) {
            int c = idx >> 7, il = idx & 127;
            g_Spart[(size_t)(it * NCLUST + c) * N_SAMPLES + jBase + il] =
                SaccJ[il * SPAD + c];
        }
    }
}

// ---------------------------------------------------------------------------
__global__ void reduce_kernel() {
    const int t = blockIdx.x * 256 + threadIdx.x;   // t = c*8192 + i
    float s = 0.f;
#pragma unroll
    for (int p = 0; p < NTILES; p++)
        s += g_Spart[(size_t)p * NCLUST * N_SAMPLES + t];
    g_S[t] = s;
}

__global__ void score_kernel() {
    const int i = blockIdx.x * 256 + threadIdx.x;
    __shared__ int scounts[NCLUST];
    if (threadIdx.x < NCLUST) scounts[threadIdx.x] = g_counts[threadIdx.x];
    __syncthreads();

    const int own = g_labS[i];
    float Sown = 0.f, b = FLT_MAX;
#pragma unroll
    for (int c = 0; c < NCLUST; c++) {
        float s = g_S[(size_t)c * N_SAMPLES + i];
        int cnt = scounts[c];
        if (c == own) Sown = s;
        else if (cnt > 0) b = fminf(b, s / (float)cnt);
    }
    const int ocnt = scounts[own];
    const float a = Sown / fmaxf((float)ocnt - 1.f, 1.f);
    float score = 0.f;
    if (ocnt > 1) score = (b - a) / fmaxf(b, a);

    __shared__ float red[256];
    red[threadIdx.x] = score;
    __syncthreads();
    for (int s = 128; s > 0; s >>= 1) {
        if (threadIdx.x < s) red[threadIdx.x] += red[threadIdx.x + s];
        __syncthreads();
    }
    if (threadIdx.x == 0) g_partial[blockIdx.x] = red[0];
}

__global__ void final_kernel(float* out) {
    if (threadIdx.x == 0) {
        float s = 0.f;
#pragma unroll
        for (int b = 0; b < 32; b++) s += g_partial[b];
        out[0] = s / (float)N_SAMPLES;
    }
}

// ---------------------------------------------------------------------------
extern "C" void kernel_launch(void* const* d_in, const int* in_sizes, int n_in,
                              void* d_out, int out_size) {
    const float* F = (const float*)d_in[0];
    const int* Lraw = (const int*)d_in[1];
    float* out = (float*)d_out;

    const int smem_bytes = SMEM_FLOATS * 4;   // ~97 KB -> 2 CTAs/SM
    cudaFuncSetAttribute(dist_kernel,
                         cudaFuncAttributeMaxDynamicSharedMemorySize, smem_bytes);

    conv_labels_kernel<<<1, 256>>>(Lraw);
    sort_kernel<<<1, 256>>>();
    gather_kernel<<<N_SAMPLES / 8, 256>>>(F);
    dim3 tgrid(N_SAMPLES / 32, DIM / 32);
    transpose_kernel<<<tgrid, dim3(32, 8)>>>();
    dim3 grid(NTILES, NTILES);
    dist_kernel<<<grid, 256, smem_bytes>>>();
    reduce_kernel<<<NCLUST * N_SAMPLES / 256, 256>>>();
    score_kernel<<<N_SAMPLES / 256, 256>>>();
    final_kernel<<<1, 32>>>(out);
}